// round 5
// baseline (speedup 1.0000x reference)
#include <cuda_runtime.h>
#include <math.h>

#define NN 50000
#define EE 600000
#define DD 128
#define HH 8
// SCALE = sqrt(DH) = sqrt(16) = 4  -> multiply by 0.25f

// -------------------- scratch (device globals; no allocation) --------------------
__device__ float g_Q[(size_t)NN * DD];
__device__ float g_K[(size_t)NN * DD];
__device__ float g_V[(size_t)NN * DD];
__device__ float g_acc[(size_t)NN * DD];     // unnormalized sum of s_exp * V
__device__ float g_scores[(size_t)EE * HH];
__device__ float g_nodemax[NN];
__device__ float g_ssum[(size_t)NN * HH];
__device__ int   g_is64;                     // edge_index dtype flag (1 = int64, 0 = int32)

// -------------------- helpers --------------------
__device__ __forceinline__ void atomicMaxF(float* addr, float v) {
    if (v >= 0.0f) {
        atomicMax((int*)addr, __float_as_int(v));
    } else {
        atomicMin((unsigned int*)addr, __float_as_uint(v));
    }
}

__device__ __forceinline__ void redAdd4(float* addr, float4 v) {
    asm volatile("red.global.add.v4.f32 [%0], {%1, %2, %3, %4};"
                 :: "l"(addr), "f"(v.x), "f"(v.y), "f"(v.z), "f"(v.w)
                 : "memory");
}

// Load edge index at logical position pos (handles int32 or int64 storage).
__device__ __forceinline__ int load_idx(const void* ei, int is64, int pos) {
    if (is64) return (int)((const long long*)ei)[pos];
    return ((const int*)ei)[pos];
}

// -------------------- init + dtype probe --------------------
__global__ void init_kernel(const void* ei) {
    int i = blockIdx.x * blockDim.x + threadIdx.x;
    if (i == 0) {
        // Probe: interpret first 64 values as int64. If all land in [0, NN),
        // storage is int64; with int32 storage the high words are random
        // node ids, so at least one combined value is out of range.
        const long long* p = (const long long*)ei;
        int ok = 1;
        for (int t = 0; t < 64; t++) {
            long long v = p[t];
            if (v < 0 || v >= NN) { ok = 0; break; }
        }
        g_is64 = ok;
    }
    if (i < NN * DD) g_acc[i] = 0.0f;
    if (i < NN * HH) g_ssum[i] = 0.0f;
    if (i < NN)      g_nodemax[i] = -INFINITY;
}

// -------------------- SGEMM: C[n,:] = A[n,:] @ W + b --------------------
// BM=64, BN=128 (full), BK=16, 256 threads, each thread TM=8 x TN=4.
// mode: 0 -> C=g_Q, A=Aext(x); 1 -> g_K; 2 -> g_V;
//       3 -> A=g_acc scaled by 1/(g_ssum+1e-8), C=Cext(out)
__global__ __launch_bounds__(256)
void gemm128(const float* __restrict__ Aext,
             const float* __restrict__ W,
             const float* __restrict__ bias,
             float* __restrict__ Cext,
             int mode)
{
    const float* A = (mode == 3) ? g_acc : Aext;
    float* C;
    if (mode == 0) C = g_Q;
    else if (mode == 1) C = g_K;
    else if (mode == 2) C = g_V;
    else C = Cext;

    __shared__ float As[16][65];    // padded: transposed x tile
    __shared__ float Bs[16][128];   // W tile

    const int tid  = threadIdx.x;
    const int row0 = blockIdx.x * 64;

    const int arow = tid >> 2;          // 0..63
    const int acol = (tid & 3) << 2;    // 0,4,8,12
    const int brow = tid >> 5;          // 0..7
    const int bcol = (tid & 31) << 2;   // 0..124
    const int tr   = tid >> 5;          // warp id: row group 0..7
    const int tc   = tid & 31;          // lane: col group 0..31

    float acc[8][4];
#pragma unroll
    for (int i = 0; i < 8; i++)
#pragma unroll
        for (int j = 0; j < 4; j++) acc[i][j] = 0.0f;

    const int  gr  = row0 + arow;
    const bool aok = (gr < NN);

    for (int k0 = 0; k0 < DD; k0 += 16) {
        float4 av = make_float4(0.f, 0.f, 0.f, 0.f);
        if (aok) {
            av = *(const float4*)(A + (size_t)gr * DD + k0 + acol);
            if (mode == 3) {
                // head index constant within this float4 (16 | head block)
                float s = 1.0f / (g_ssum[gr * HH + ((k0 + acol) >> 4)] + 1e-8f);
                av.x *= s; av.y *= s; av.z *= s; av.w *= s;
            }
        }
        As[acol + 0][arow] = av.x;
        As[acol + 1][arow] = av.y;
        As[acol + 2][arow] = av.z;
        As[acol + 3][arow] = av.w;

        float4 b0 = *(const float4*)(W + (size_t)(k0 + brow) * DD + bcol);
        float4 b1 = *(const float4*)(W + (size_t)(k0 + brow + 8) * DD + bcol);
        *(float4*)&Bs[brow][bcol]     = b0;
        *(float4*)&Bs[brow + 8][bcol] = b1;

        __syncthreads();

#pragma unroll
        for (int k = 0; k < 16; k++) {
            float a[8];
#pragma unroll
            for (int i = 0; i < 8; i++) a[i] = As[k][tr * 8 + i];   // warp-broadcast
            float4 bv = *(const float4*)&Bs[k][tc * 4];
#pragma unroll
            for (int i = 0; i < 8; i++) {
                acc[i][0] += a[i] * bv.x;
                acc[i][1] += a[i] * bv.y;
                acc[i][2] += a[i] * bv.z;
                acc[i][3] += a[i] * bv.w;
            }
        }
        __syncthreads();
    }

    float4 bb = *(const float4*)(bias + tc * 4);
#pragma unroll
    for (int i = 0; i < 8; i++) {
        int r = row0 + tr * 8 + i;
        if (r < NN) {
            float4 o = make_float4(acc[i][0] + bb.x, acc[i][1] + bb.y,
                                   acc[i][2] + bb.z, acc[i][3] + bb.w);
            *(float4*)(C + (size_t)r * DD + tc * 4) = o;
        }
    }
}

// -------------------- pass 1: scores + segment max (warp per edge) --------------------
__global__ __launch_bounds__(256)
void edge_score(const void* __restrict__ ei, const float* __restrict__ ea)
{
    int e = (int)((blockIdx.x * (unsigned)blockDim.x + threadIdx.x) >> 5);
    if (e >= EE) return;
    const int lane = threadIdx.x & 31;
    const int is64 = g_is64;

    const int row = load_idx(ei, is64, e);        // warp-uniform broadcast load
    const int col = load_idx(ei, is64, EE + e);

    float4 q = ((const float4*)g_Q)[(size_t)row * 32 + lane];
    float4 k = ((const float4*)g_K)[(size_t)col * 32 + lane];
    float d = q.x * k.x + q.y * k.y + q.z * k.z + q.w * k.w;
    // reduce within groups of 4 lanes (DH=16 = 4 lanes x float4)
    d += __shfl_xor_sync(0xffffffffu, d, 1);
    d += __shfl_xor_sync(0xffffffffu, d, 2);

    const float score = d * 0.25f + ea[e];
    const int h = lane >> 2;
    if ((lane & 3) == 0) g_scores[(size_t)e * HH + h] = score;

    float m = ((lane & 3) == 0) ? score : -3.402823466e38f;
    m = fmaxf(m, __shfl_xor_sync(0xffffffffu, m, 4));
    m = fmaxf(m, __shfl_xor_sync(0xffffffffu, m, 8));
    m = fmaxf(m, __shfl_xor_sync(0xffffffffu, m, 16));
    if (lane == 0) atomicMaxF(&g_nodemax[row], m);
}

// -------------------- pass 2: exp + segment sums + weighted V scatter --------------------
__global__ __launch_bounds__(256)
void edge_agg(const void* __restrict__ ei)
{
    int e = (int)((blockIdx.x * (unsigned)blockDim.x + threadIdx.x) >> 5);
    if (e >= EE) return;
    const int lane = threadIdx.x & 31;
    const int is64 = g_is64;

    const int row = load_idx(ei, is64, e);
    const int col = load_idx(ei, is64, EE + e);
    const int h = lane >> 2;

    const float sc = g_scores[(size_t)e * HH + h];   // 4-lane broadcast
    const float sexp = __expf(sc - g_nodemax[row]);

    if ((lane & 3) == 0) atomicAdd(&g_ssum[row * HH + h], sexp);

    float4 v = ((const float4*)g_V)[(size_t)col * 32 + lane];
    float4 o = make_float4(v.x * sexp, v.y * sexp, v.z * sexp, v.w * sexp);
    redAdd4(g_acc + (size_t)row * DD + lane * 4, o);
}

// -------------------- launch --------------------
extern "C" void kernel_launch(void* const* d_in, const int* in_sizes, int n_in,
                              void* d_out, int out_size)
{
    const float* x  = (const float*)d_in[0];
    const void*  ei = d_in[1];
    const float* ea = (const float*)d_in[2];
    const float* Wq = (const float*)d_in[3];
    const float* bq = (const float*)d_in[4];
    const float* Wk = (const float*)d_in[5];
    const float* bk = (const float*)d_in[6];
    const float* Wv = (const float*)d_in[7];
    const float* bv = (const float*)d_in[8];
    const float* Wo = (const float*)d_in[9];
    const float* bo = (const float*)d_in[10];
    float* out = (float*)d_out;

    const int gemm_blocks = (NN + 63) / 64;
    const int edge_blocks = (EE * 32 + 255) / 256;

    init_kernel<<<(NN * DD + 255) / 256, 256>>>(ei);
    gemm128<<<gemm_blocks, 256>>>(x, Wq, bq, nullptr, 0);
    gemm128<<<gemm_blocks, 256>>>(x, Wk, bk, nullptr, 1);
    gemm128<<<gemm_blocks, 256>>>(x, Wv, bv, nullptr, 2);
    edge_score<<<edge_blocks, 256>>>(ei, ea);
    edge_agg<<<edge_blocks, 256>>>(ei);
    gemm128<<<gemm_blocks, 256>>>(nullptr, Wo, bo, out, 3);
}